// round 2
// baseline (speedup 1.0000x reference)
#include <cuda_runtime.h>
#include <math.h>

#define N_NODES 50000
#define N_EDGES 800000
#define TOT_E   (N_EDGES + N_NODES)
#define HID     128
#define NGR     512
#define QSD     256       // 2*HID
#define NCLS    10

// ---------------- scratch (device globals; no runtime allocation) ----------------
__device__ int   g_cnt[N_NODES];          // in-degree incl self loop
__device__ float g_dis[N_NODES];          // rsqrt(deg)
__device__ int   g_gptr[NGR + 1];         // per-graph node ranges (batch sorted)
__device__ float g_agg[N_NODES * HID];    // scatter buffer A
__device__ float g_agg2[N_NODES * HID];   // scatter buffer B
__device__ float g_hA[N_NODES * HID];
__device__ float g_hB[N_NODES * HID];
__device__ float g_escr[N_NODES];
__device__ float g_WT[384 * 512];         // transposed [Wih|Whh]
__device__ float g_gbias[512];            // bih+bhh
__device__ float g_gates[NGR * 512];
__device__ float g_hs[NGR * HID];
__device__ float g_cs[NGR * HID];
__device__ float g_qstar[NGR * QSD];
__device__ float g_y1[NGR * HID];
__device__ float g_y2[NGR * 64];

// ---------------- init: zero states + scatter buffer A, cnt=1 (self loop) ----------------
__global__ void k_init() {
    int idx = blockIdx.x * blockDim.x + threadIdx.x;   // 1.6M threads
    if (idx < N_NODES * HID / 4)
        ((float4*)g_agg)[idx] = make_float4(0.f, 0.f, 0.f, 0.f);
    if (idx < N_NODES) g_cnt[idx] = 1;
    if (idx < NGR * HID) { g_hs[idx] = 0.f; g_cs[idx] = 0.f; }
    if (idx < NGR * QSD) g_qstar[idx] = 0.f;
}

__global__ void k_hist(const int* __restrict__ ei) {
    int e = blockIdx.x * blockDim.x + threadIdx.x;
    if (e < N_EDGES) atomicAdd(&g_cnt[ei[N_EDGES + e]], 1);
}

__global__ void k_prep() {
    int i = blockIdx.x * blockDim.x + threadIdx.x;
    if (i < N_NODES) g_dis[i] = rsqrtf((float)g_cnt[i]);
}

// ---------------- edge-parallel scatter SpMM: out[tgt] += dis[src]*dis[tgt]*in[src] ----------------
// one warp per edge; lane handles 4 floats via float4 vector reduction (sm_90+)
__global__ void k_spmm(const float* __restrict__ in, float* __restrict__ out,
                       const int* __restrict__ ei) {
    int w = blockIdx.x * 8 + (threadIdx.x >> 5);
    int lane = threadIdx.x & 31;
    if (w >= TOT_E) return;
    int src, tgt;
    if (w < N_EDGES) { src = ei[w]; tgt = ei[N_EDGES + w]; }
    else { src = tgt = w - N_EDGES; }        // self loop
    float wt = g_dis[src] * g_dis[tgt];
    float4 v = ((const float4*)in)[src * 32 + lane];
    v.x *= wt; v.y *= wt; v.z *= wt; v.w *= wt;
    atomicAdd(&((float4*)out)[tgt * 32 + lane], v);
}

// ---------------- dense GEMM (50000x128 @ 128x128) + bias + relu; fused zero of next buffer ----------------
// block: 64 rows x 128 cols; 256 threads; thread: 16 rows x 2 cols
__global__ void __launch_bounds__(256) k_gemm_relu(
        const float* __restrict__ A, const float* __restrict__ W,
        const float* __restrict__ bias, float* __restrict__ C,
        float* __restrict__ Z) {
    __shared__ float As[64 * 128];
    int tid = threadIdx.x;
    int r0 = blockIdx.x * 64;
    // fused: zero this block's row range of the next scatter buffer
    if (Z) {
        int nrow = N_NODES - r0; if (nrow > 64) nrow = 64;
        float4* z4 = (float4*)Z + r0 * 32;
        for (int idx = tid; idx < nrow * 32; idx += 256)
            z4[idx] = make_float4(0.f, 0.f, 0.f, 0.f);
    }
    for (int idx = tid; idx < 64 * 128; idx += 256) {
        int r = idx >> 7, k = idx & 127;
        As[idx] = (r0 + r < N_NODES) ? A[(r0 + r) * 128 + k] : 0.f;
    }
    __syncthreads();
    int j0 = tid & 63;
    int rg = tid >> 6;            // 0..3, 16 rows each
    const float* Asb = &As[rg * 16 * 128];
    float acc0[16], acc1[16];
    #pragma unroll
    for (int r = 0; r < 16; r++) { acc0[r] = 0.f; acc1[r] = 0.f; }
    #pragma unroll 4
    for (int k = 0; k < 128; k++) {
        float w0 = W[k * 128 + j0];
        float w1 = W[k * 128 + j0 + 64];
        #pragma unroll
        for (int r = 0; r < 16; r++) {
            float a = Asb[r * 128 + k];
            acc0[r] += a * w0;
            acc1[r] += a * w1;
        }
    }
    float b0 = bias[j0], b1 = bias[j0 + 64];
    #pragma unroll
    for (int r = 0; r < 16; r++) {
        int rr = r0 + rg * 16 + r;
        if (rr < N_NODES) {
            C[rr * 128 + j0]      = fmaxf(acc0[r] + b0, 0.f);
            C[rr * 128 + j0 + 64] = fmaxf(acc1[r] + b1, 0.f);
        }
    }
}

// ---------------- per-graph ranges by binary search on sorted batch ----------------
__global__ void k_gptr_bs(const int* __restrict__ batch) {
    int g = blockIdx.x * blockDim.x + threadIdx.x;
    if (g > NGR) return;
    if (g == NGR) { g_gptr[g] = N_NODES; return; }
    int lo = 0, hi = N_NODES;
    while (lo < hi) {
        int mid = (lo + hi) >> 1;
        if (batch[mid] < g) lo = mid + 1; else hi = mid;
    }
    g_gptr[g] = lo;
}

__global__ void k_trans(const float* __restrict__ Wih, const float* __restrict__ Whh,
                        const float* __restrict__ bih, const float* __restrict__ bhh) {
    int idx = blockIdx.x * blockDim.x + threadIdx.x;
    if (idx < 384 * 512) {
        int k = idx / 512, j = idx % 512;
        g_WT[idx] = (k < 256) ? Wih[j * 256 + k] : Whh[j * 128 + (k - 256)];
    }
    if (idx < 512) g_gbias[idx] = bih[idx] + bhh[idx];
}

// ---------------- Set2Set: LSTM gates GEMM (512x512x384) ----------------
__global__ void k_gates() {
    __shared__ float As[16 * 384];
    int tid = threadIdx.x;
    int jb = blockIdx.x, gb = blockIdx.y;
    for (int idx = tid; idx < 16 * 384; idx += 128) {
        int g = idx / 384, k = idx % 384;
        int gg = gb * 16 + g;
        As[idx] = (k < 256) ? g_qstar[gg * 256 + k] : g_hs[gg * 128 + (k - 256)];
    }
    __syncthreads();
    int j = jb * 128 + tid;
    float acc[16];
    #pragma unroll
    for (int g = 0; g < 16; g++) acc[g] = 0.f;
    #pragma unroll 4
    for (int k = 0; k < 384; k++) {
        float wv = g_WT[k * 512 + j];
        #pragma unroll
        for (int g = 0; g < 16; g++) acc[g] += As[g * 384 + k] * wv;
    }
    float bb = g_gbias[j];
    #pragma unroll
    for (int g = 0; g < 16; g++) g_gates[(gb * 16 + g) * 512 + j] = acc[g] + bb;
}

__device__ __forceinline__ float sigmoidf_(float x) { return 1.f / (1.f + expf(-x)); }

__global__ void k_lstm() {
    int idx = blockIdx.x * blockDim.x + threadIdx.x;
    if (idx >= NGR * HID) return;
    int g = idx >> 7, j = idx & 127;
    const float* gr = &g_gates[g * 512];
    float ig = gr[j], fg = gr[j + 128], gg = gr[j + 256], og = gr[j + 384];
    float c = sigmoidf_(fg) * g_cs[idx] + sigmoidf_(ig) * tanhf(gg);
    g_cs[idx] = c;
    float q = sigmoidf_(og) * tanhf(c);
    g_hs[idx] = q;
    g_qstar[g * 256 + j] = q;   // q part of q_star
}

// ---------------- attention + segment softmax + weighted sum (block per graph) ----------------
__global__ void k_attn(const float* __restrict__ h) {
    __shared__ float4 sq4[32];
    __shared__ float swmax[4];
    __shared__ float semax;
    float* sq = (float*)sq4;
    int g = blockIdx.x;
    int tid = threadIdx.x;
    int lane = tid & 31, warp = tid >> 5;
    sq[tid] = g_hs[g * 128 + tid];
    __syncthreads();
    int s = g_gptr[g], e = g_gptr[g + 1];
    if (s >= e) {                        // empty graph -> r = 0
        g_qstar[g * 256 + 128 + tid] = 0.f;
        return;
    }
    // pass 1: e_i = <h_i, q>, track max (warp per node)
    float lmax = -INFINITY;
    float4 qv = sq4[lane];
    const float4* h4 = (const float4*)h;
    for (int i = s + warp; i < e; i += 4) {
        float4 hv = h4[i * 32 + lane];
        float d = hv.x * qv.x + hv.y * qv.y + hv.z * qv.z + hv.w * qv.w;
        #pragma unroll
        for (int o = 16; o > 0; o >>= 1) d += __shfl_xor_sync(0xffffffffu, d, o);
        if (lane == 0) g_escr[i] = d;
        lmax = fmaxf(lmax, d);
    }
    if (lane == 0) swmax[warp] = lmax;
    __syncthreads();
    if (tid == 0)
        semax = fmaxf(fmaxf(swmax[0], swmax[1]), fmaxf(swmax[2], swmax[3]));
    __syncthreads();
    float emax = semax;
    // pass 2: thread d accumulates r_d
    float r = 0.f, asum = 0.f;
    #pragma unroll 4
    for (int i = s; i < e; i++) {
        float w = __expf(g_escr[i] - emax);
        asum += w;
        r += w * h[i * 128 + tid];
    }
    g_qstar[g * 256 + 128 + tid] = r / (asum > 0.f ? asum : 1.f);
}

// ---------------- MLP head ----------------
__global__ void k_mlp1(const float* __restrict__ L1w, const float* __restrict__ L1b) {
    __shared__ float a[256];
    int g = blockIdx.x, j = threadIdx.x;
    a[j] = g_qstar[g * 256 + j];
    a[j + 128] = g_qstar[g * 256 + 128 + j];
    __syncthreads();
    float acc = L1b[j];
    #pragma unroll 4
    for (int k = 0; k < 256; k++) acc += a[k] * L1w[k * 128 + j];
    g_y1[g * 128 + j] = fmaxf(acc, 0.f);
}

__global__ void k_mlp2(const float* __restrict__ L2w, const float* __restrict__ L2b) {
    __shared__ float a[128];
    int g = blockIdx.x, j = threadIdx.x;
    a[j] = g_y1[g * 128 + j];
    a[j + 64] = g_y1[g * 128 + 64 + j];
    __syncthreads();
    float acc = L2b[j];
    #pragma unroll 4
    for (int k = 0; k < 128; k++) acc += a[k] * L2w[k * 64 + j];
    g_y2[g * 64 + j] = fmaxf(acc, 0.f);
}

__global__ void k_mlp3(const float* __restrict__ L3w, const float* __restrict__ L3b,
                       float* __restrict__ out) {
    __shared__ float a[64];
    __shared__ float ys[NCLS];
    int g = blockIdx.x, j = threadIdx.x;   // 32 threads
    a[j] = g_y2[g * 64 + j];
    a[j + 32] = g_y2[g * 64 + 32 + j];
    __syncthreads();
    if (j < NCLS) {
        float acc = L3b[j];
        #pragma unroll
        for (int k = 0; k < 64; k++) acc += a[k] * L3w[k * NCLS + j];
        ys[j] = acc;
    }
    __syncthreads();
    if (j < NCLS) {
        float m = ys[0];
        #pragma unroll
        for (int k = 1; k < NCLS; k++) m = fmaxf(m, ys[k]);
        float se = 0.f;
        #pragma unroll
        for (int k = 0; k < NCLS; k++) se += expf(ys[k] - m);
        out[g * NCLS + j] = ys[j] - m - logf(se);
    }
}

// ---------------- launcher ----------------
extern "C" void kernel_launch(void* const* d_in, const int* in_sizes, int n_in,
                              void* d_out, int out_size) {
    const float* x     = (const float*)d_in[0];
    const int*   ei    = (const int*)  d_in[1];
    const int*   batch = (const int*)  d_in[2];
    const float* W1 = (const float*)d_in[3];  const float* b1 = (const float*)d_in[4];
    const float* W2 = (const float*)d_in[5];  const float* b2 = (const float*)d_in[6];
    const float* W3 = (const float*)d_in[7];  const float* b3 = (const float*)d_in[8];
    const float* Wih = (const float*)d_in[9]; const float* Whh = (const float*)d_in[10];
    const float* bih = (const float*)d_in[11];const float* bhh = (const float*)d_in[12];
    const float* L1w = (const float*)d_in[13];const float* L1b = (const float*)d_in[14];
    const float* L2w = (const float*)d_in[15];const float* L2b = (const float*)d_in[16];
    const float* L3w = (const float*)d_in[17];const float* L3b = (const float*)d_in[18];
    float* out = (float*)d_out;

    int spmm_grid = (TOT_E + 7) / 8;
    int gemm_grid = (N_NODES + 63) / 64;

    // launch 0-2: init, degree, norm
    k_init<<<(N_NODES * HID / 4 + 255) / 256, 256>>>();
    k_hist<<<(N_EDGES + 255) / 256, 256>>>(ei);
    k_prep<<<(N_NODES + 255) / 256, 256>>>();

    // launches 3..8: SpMM at 3/5/7, GEMM at 4/6/8 (profiler-friendly ordering)
    k_spmm<<<spmm_grid, 256>>>(x, g_agg, ei);
    k_gemm_relu<<<gemm_grid, 256>>>(g_agg, W1, b1, g_hA, g_agg2);
    k_spmm<<<spmm_grid, 256>>>(g_hA, g_agg2, ei);
    k_gemm_relu<<<gemm_grid, 256>>>(g_agg2, W2, b2, g_hB, g_agg);
    k_spmm<<<spmm_grid, 256>>>(g_hB, g_agg, ei);
    k_gemm_relu<<<gemm_grid, 256>>>(g_agg, W3, b3, g_hA, (float*)0);

    // graph ranges + LSTM weight prep
    k_gptr_bs<<<3, 256>>>(batch);
    k_trans<<<(384 * 512 + 255) / 256, 256>>>(Wih, Whh, bih, bhh);

    // Set2Set (4 processing steps); final node embedding = g_hA
    for (int step = 0; step < 4; step++) {
        k_gates<<<dim3(4, 32), 128>>>();
        k_lstm<<<(NGR * HID + 255) / 256, 256>>>();
        k_attn<<<NGR, 128>>>(g_hA);
    }

    // MLP head + log_softmax
    k_mlp1<<<NGR, 128>>>(L1w, L1b);
    k_mlp2<<<NGR, 64>>>(L2w, L2b);
    k_mlp3<<<NGR, 32>>>(L3w, L3b, out);
}

// round 4
// speedup vs baseline: 2.1204x; 2.1204x over previous
#include <cuda_runtime.h>
#include <math.h>

#define N_NODES 50000
#define N_EDGES 800000
#define TOT_E   (N_EDGES + N_NODES)
#define HID     128
#define NGR     512
#define QSD     256       // 2*HID
#define NCLS    10

// ---------------- scratch (device globals; no runtime allocation) ----------------
__device__ int   g_cnt[N_NODES];          // edge-count histogram (zero at load & after each run)
__device__ int   g_rowptr[N_NODES + 1];
__device__ int   g_cursor[N_NODES];
__device__ float g_dis[N_NODES];          // rsqrt(deg incl self-loop)
__device__ int2  g_edges[TOT_E];          // CSR by target: {src, weight-as-int}
__device__ int   g_gptr[NGR + 1];         // per-graph node ranges (batch sorted)
__device__ float g_hA[N_NODES * HID];
__device__ float g_hB[N_NODES * HID];
__device__ float g_escr[N_NODES];
__device__ float g_WT[384 * 512];         // transposed [Wih|Whh]
__device__ float g_gbias[512];            // bih+bhh
__device__ float g_gates[NGR * 512];
__device__ float g_hs[NGR * HID];
__device__ float g_cs[NGR * HID];
__device__ float g_qstar[NGR * QSD];
__device__ float g_y1[NGR * HID];
__device__ float g_y2[NGR * 64];

// ---------------- launch 0: degree histogram (g_cnt is 0 on entry; see k_reset) ----------------
__global__ void k_hist(const int* __restrict__ ei) {
    int e = blockIdx.x * blockDim.x + threadIdx.x;
    if (e < N_EDGES) atomicAdd(&g_cnt[ei[N_EDGES + e]], 1);
}

// ---------------- launch 1: single-block scan -> rowptr, cursor, dis ----------------
__global__ void k_scanall() {           // <<<1, 1024>>>
    __shared__ int s[1024];
    const int CH = (N_NODES + 1023) / 1024;   // 49
    int t = threadIdx.x;
    int base = t * CH;
    int sum = 0;
    for (int j = 0; j < CH; j++) {
        int i = base + j;
        if (i < N_NODES) sum += g_cnt[i] + 1;       // +1 self loop
    }
    s[t] = sum;
    __syncthreads();
    for (int off = 1; off < 1024; off <<= 1) {
        int v = 0;
        if (t >= off) v = s[t - off];
        __syncthreads();
        s[t] += v;
        __syncthreads();
    }
    int run = s[t] - sum;               // exclusive prefix for this thread's chunk
    for (int j = 0; j < CH; j++) {
        int i = base + j;
        if (i < N_NODES) {
            int deg = g_cnt[i] + 1;
            g_rowptr[i] = run;
            g_cursor[i] = run;
            g_dis[i] = rsqrtf((float)deg);
            run += deg;
        }
    }
    if (t == 1023) g_rowptr[N_NODES] = s[1023];
}

// ---------------- launch 2: fill CSR with precomputed weights ----------------
__global__ void k_fill(const int* __restrict__ ei) {
    int idx = blockIdx.x * blockDim.x + threadIdx.x;
    if (idx >= TOT_E) return;
    int src, tgt; float w;
    if (idx < N_EDGES) {
        src = ei[idx]; tgt = ei[N_EDGES + idx];
        w = g_dis[src] * g_dis[tgt];
    } else {
        src = tgt = idx - N_EDGES;
        float d = g_dis[src];
        w = d * d;
    }
    int pos = atomicAdd(&g_cursor[tgt], 1);
    g_edges[pos] = make_int2(src, __float_as_int(w));
}

// ---------------- launches 3-5: fused GCN layer: gather (CSR) -> GEMM -> bias+relu ----------------
// block = 64 rows x 128 cols, 256 threads
__global__ void __launch_bounds__(256) k_layer(
        const float* __restrict__ in, const float* __restrict__ W,
        const float* __restrict__ bias, float* __restrict__ out) {
    __shared__ float As[64 * 128];
    int tid = threadIdx.x, lane = tid & 31, wp = tid >> 5;
    int r0 = blockIdx.x * 64;
    const float4* in4 = (const float4*)in;
    // gather phase: warp per row, lane covers 4 features
    for (int rr = wp; rr < 64; rr += 8) {
        int i = r0 + rr;
        float4 acc = make_float4(0.f, 0.f, 0.f, 0.f);
        if (i < N_NODES) {
            int s = g_rowptr[i], e = g_rowptr[i + 1];
            #pragma unroll 4
            for (int idx = s; idx < e; idx++) {
                int2 ed = g_edges[idx];
                float wt = __int_as_float(ed.y);
                float4 v = in4[ed.x * 32 + lane];
                acc.x += wt * v.x; acc.y += wt * v.y;
                acc.z += wt * v.z; acc.w += wt * v.w;
            }
        }
        ((float4*)(As + rr * 128))[lane] = acc;
    }
    __syncthreads();
    // GEMM phase: thread = 16 rows x 2 cols
    int j0 = tid & 63;
    int rg = tid >> 6;
    const float* Asb = &As[rg * 16 * 128];
    float acc0[16], acc1[16];
    #pragma unroll
    for (int r = 0; r < 16; r++) { acc0[r] = 0.f; acc1[r] = 0.f; }
    #pragma unroll 4
    for (int k = 0; k < 128; k++) {
        float w0 = W[k * 128 + j0];
        float w1 = W[k * 128 + j0 + 64];
        #pragma unroll
        for (int r = 0; r < 16; r++) {
            float a = Asb[r * 128 + k];
            acc0[r] += a * w0;
            acc1[r] += a * w1;
        }
    }
    float b0 = bias[j0], b1 = bias[j0 + 64];
    #pragma unroll
    for (int r = 0; r < 16; r++) {
        int rr = r0 + rg * 16 + r;
        if (rr < N_NODES) {
            out[rr * 128 + j0]      = fmaxf(acc0[r] + b0, 0.f);
            out[rr * 128 + j0 + 64] = fmaxf(acc1[r] + b1, 0.f);
        }
    }
}

// ---------------- set2set state init ----------------
__global__ void k_init_states() {
    int idx = blockIdx.x * blockDim.x + threadIdx.x;
    if (idx < NGR * HID) { g_hs[idx] = 0.f; g_cs[idx] = 0.f; }
    if (idx < NGR * QSD) g_qstar[idx] = 0.f;
}

// ---------------- per-graph ranges by binary search on sorted batch ----------------
__global__ void k_gptr_bs(const int* __restrict__ batch) {
    int g = blockIdx.x * blockDim.x + threadIdx.x;
    if (g > NGR) return;
    if (g == NGR) { g_gptr[g] = N_NODES; return; }
    int lo = 0, hi = N_NODES;
    while (lo < hi) {
        int mid = (lo + hi) >> 1;
        if (batch[mid] < g) lo = mid + 1; else hi = mid;
    }
    g_gptr[g] = lo;
}

__global__ void k_trans(const float* __restrict__ Wih, const float* __restrict__ Whh,
                        const float* __restrict__ bih, const float* __restrict__ bhh) {
    int idx = blockIdx.x * blockDim.x + threadIdx.x;
    if (idx < 384 * 512) {
        int k = idx / 512, j = idx % 512;
        g_WT[idx] = (k < 256) ? Wih[j * 256 + k] : Whh[j * 128 + (k - 256)];
    }
    if (idx < 512) g_gbias[idx] = bih[idx] + bhh[idx];
}

// ---------------- Set2Set: LSTM gates GEMM (512x512x384) ----------------
__global__ void k_gates() {
    __shared__ float As[16 * 384];
    int tid = threadIdx.x;
    int jb = blockIdx.x, gb = blockIdx.y;
    for (int idx = tid; idx < 16 * 384; idx += 128) {
        int g = idx / 384, k = idx % 384;
        int gg = gb * 16 + g;
        As[idx] = (k < 256) ? g_qstar[gg * 256 + k] : g_hs[gg * 128 + (k - 256)];
    }
    __syncthreads();
    int j = jb * 128 + tid;
    float acc[16];
    #pragma unroll
    for (int g = 0; g < 16; g++) acc[g] = 0.f;
    #pragma unroll 4
    for (int k = 0; k < 384; k++) {
        float wv = g_WT[k * 512 + j];
        #pragma unroll
        for (int g = 0; g < 16; g++) acc[g] += As[g * 384 + k] * wv;
    }
    float bb = g_gbias[j];
    #pragma unroll
    for (int g = 0; g < 16; g++) g_gates[(gb * 16 + g) * 512 + j] = acc[g] + bb;
}

__device__ __forceinline__ float sigmoidf_(float x) { return 1.f / (1.f + expf(-x)); }

__global__ void k_lstm() {
    int idx = blockIdx.x * blockDim.x + threadIdx.x;
    if (idx >= NGR * HID) return;
    int g = idx >> 7, j = idx & 127;
    const float* gr = &g_gates[g * 512];
    float ig = gr[j], fg = gr[j + 128], gg = gr[j + 256], og = gr[j + 384];
    float c = sigmoidf_(fg) * g_cs[idx] + sigmoidf_(ig) * tanhf(gg);
    g_cs[idx] = c;
    float q = sigmoidf_(og) * tanhf(c);
    g_hs[idx] = q;
    g_qstar[g * 256 + j] = q;   // q part of q_star
}

// ---------------- attention + segment softmax + weighted sum (block per graph) ----------------
__global__ void k_attn(const float* __restrict__ h) {
    __shared__ float4 sq4[32];
    __shared__ float swmax[4];
    __shared__ float semax;
    float* sq = (float*)sq4;
    int g = blockIdx.x;
    int tid = threadIdx.x;
    int lane = tid & 31, warp = tid >> 5;
    sq[tid] = g_hs[g * 128 + tid];
    __syncthreads();
    int s = g_gptr[g], e = g_gptr[g + 1];
    if (s >= e) {                        // empty graph -> r = 0
        g_qstar[g * 256 + 128 + tid] = 0.f;
        return;
    }
    float lmax = -INFINITY;
    float4 qv = sq4[lane];
    const float4* h4 = (const float4*)h;
    for (int i = s + warp; i < e; i += 4) {
        float4 hv = h4[i * 32 + lane];
        float d = hv.x * qv.x + hv.y * qv.y + hv.z * qv.z + hv.w * qv.w;
        #pragma unroll
        for (int o = 16; o > 0; o >>= 1) d += __shfl_xor_sync(0xffffffffu, d, o);
        if (lane == 0) g_escr[i] = d;
        lmax = fmaxf(lmax, d);
    }
    if (lane == 0) swmax[warp] = lmax;
    __syncthreads();
    if (tid == 0)
        semax = fmaxf(fmaxf(swmax[0], swmax[1]), fmaxf(swmax[2], swmax[3]));
    __syncthreads();
    float emax = semax;
    float r = 0.f, asum = 0.f;
    #pragma unroll 4
    for (int i = s; i < e; i++) {
        float w = __expf(g_escr[i] - emax);
        asum += w;
        r += w * h[i * 128 + tid];
    }
    g_qstar[g * 256 + 128 + tid] = r / (asum > 0.f ? asum : 1.f);
}

// ---------------- MLP head ----------------
__global__ void k_mlp1(const float* __restrict__ L1w, const float* __restrict__ L1b) {
    __shared__ float a[256];
    int g = blockIdx.x, j = threadIdx.x;
    a[j] = g_qstar[g * 256 + j];
    a[j + 128] = g_qstar[g * 256 + 128 + j];
    __syncthreads();
    float acc = L1b[j];
    #pragma unroll 4
    for (int k = 0; k < 256; k++) acc += a[k] * L1w[k * 128 + j];
    g_y1[g * 128 + j] = fmaxf(acc, 0.f);
}

__global__ void k_mlp2(const float* __restrict__ L2w, const float* __restrict__ L2b) {
    __shared__ float a[128];
    int g = blockIdx.x, j = threadIdx.x;
    a[j] = g_y1[g * 128 + j];
    a[j + 64] = g_y1[g * 128 + 64 + j];
    __syncthreads();
    float acc = L2b[j];
    #pragma unroll 4
    for (int k = 0; k < 128; k++) acc += a[k] * L2w[k * 64 + j];
    g_y2[g * 64 + j] = fmaxf(acc, 0.f);
}

__global__ void k_mlp3(const float* __restrict__ L3w, const float* __restrict__ L3b,
                       float* __restrict__ out) {
    __shared__ float a[64];
    __shared__ float ys[NCLS];
    int g = blockIdx.x, j = threadIdx.x;   // 32 threads
    a[j] = g_y2[g * 64 + j];
    a[j + 32] = g_y2[g * 64 + 32 + j];
    __syncthreads();
    if (j < NCLS) {
        float acc = L3b[j];
        #pragma unroll
        for (int k = 0; k < 64; k++) acc += a[k] * L3w[k * NCLS + j];
        ys[j] = acc;
    }
    __syncthreads();
    if (j < NCLS) {
        float m = ys[0];
        #pragma unroll
        for (int k = 1; k < NCLS; k++) m = fmaxf(m, ys[k]);
        float se = 0.f;
        #pragma unroll
        for (int k = 0; k < NCLS; k++) se += expf(ys[k] - m);
        out[g * NCLS + j] = ys[j] - m - logf(se);
    }
}

// ---------------- trailing reset: re-zero histogram so each replay starts clean ----------------
__global__ void k_reset() {
    int i = blockIdx.x * blockDim.x + threadIdx.x;
    if (i < N_NODES) g_cnt[i] = 0;
}

// ---------------- launcher ----------------
extern "C" void kernel_launch(void* const* d_in, const int* in_sizes, int n_in,
                              void* d_out, int out_size) {
    const float* x     = (const float*)d_in[0];
    const int*   ei    = (const int*)  d_in[1];
    const int*   batch = (const int*)  d_in[2];
    const float* W1 = (const float*)d_in[3];  const float* b1 = (const float*)d_in[4];
    const float* W2 = (const float*)d_in[5];  const float* b2 = (const float*)d_in[6];
    const float* W3 = (const float*)d_in[7];  const float* b3 = (const float*)d_in[8];
    const float* Wih = (const float*)d_in[9]; const float* Whh = (const float*)d_in[10];
    const float* bih = (const float*)d_in[11];const float* bhh = (const float*)d_in[12];
    const float* L1w = (const float*)d_in[13];const float* L1b = (const float*)d_in[14];
    const float* L2w = (const float*)d_in[15];const float* L2b = (const float*)d_in[16];
    const float* L3w = (const float*)d_in[17];const float* L3b = (const float*)d_in[18];
    float* out = (float*)d_out;

    int layer_grid = (N_NODES + 63) / 64;

    // CSR build (g_cnt arrives zeroed: module-load init, then k_reset at end of every run)
    k_hist<<<(N_EDGES + 255) / 256, 256>>>(ei);        // 0
    k_scanall<<<1, 1024>>>();                          // 1
    k_fill<<<(TOT_E + 255) / 256, 256>>>(ei);          // 2

    // fused GCN layers (index 3 = ncu capture target)
    k_layer<<<layer_grid, 256>>>(x,    W1, b1, g_hA);  // 3
    k_layer<<<layer_grid, 256>>>(g_hA, W2, b2, g_hB);  // 4
    k_layer<<<layer_grid, 256>>>(g_hB, W3, b3, g_hA);  // 5

    // set2set prep
    k_init_states<<<(NGR * QSD + 255) / 256, 256>>>(); // 6
    k_gptr_bs<<<3, 256>>>(batch);                      // 7
    k_trans<<<(384 * 512 + 255) / 256, 256>>>(Wih, Whh, bih, bhh); // 8

    // Set2Set (4 processing steps); final node embedding = g_hA
    for (int step = 0; step < 4; step++) {
        k_gates<<<dim3(4, 32), 128>>>();
        k_lstm<<<(NGR * HID + 255) / 256, 256>>>();
        k_attn<<<NGR, 128>>>(g_hA);
    }

    // MLP head + log_softmax
    k_mlp1<<<NGR, 128>>>(L1w, L1b);
    k_mlp2<<<NGR, 64>>>(L2w, L2b);
    k_mlp3<<<NGR, 32>>>(L3w, L3b, out);

    // restore invariant for next replay
    k_reset<<<(N_NODES + 255) / 256, 256>>>();
}

// round 5
// speedup vs baseline: 2.1465x; 1.0123x over previous
#include <cuda_runtime.h>
#include <math.h>

#define N_NODES 50000
#define N_EDGES 800000
#define TOT_E   (N_EDGES + N_NODES)
#define HID     128
#define NGR     512
#define QSD     256       // 2*HID
#define NCLS    10

// ---------------- scratch (device globals; no runtime allocation) ----------------
__device__ int   g_cnt[N_NODES];          // edge-count histogram (zero at load; re-zeroed inside k_fill)
__device__ int   g_rowptr[N_NODES + 1];
__device__ int   g_cursor[N_NODES];
__device__ float g_dis[N_NODES];          // rsqrt(deg incl self-loop)
__device__ int2  g_edges[TOT_E];          // CSR by target: {src, weight-as-int}
__device__ int   g_gptr[NGR + 1];         // per-graph node ranges (batch sorted)
__device__ float g_hA[N_NODES * HID];
__device__ float g_hB[N_NODES * HID];
__device__ float g_escr[N_NODES];
__device__ float g_WT[384 * 512];         // transposed [Wih|Whh]
__device__ float g_gbias[512];            // bih+bhh
__device__ float g_hs[NGR * HID];
__device__ float g_cs[NGR * HID];
__device__ float g_qstar[NGR * QSD];

// ---------------- launch 0: degree histogram ----------------
__global__ void k_hist(const int* __restrict__ ei) {
    int e = blockIdx.x * blockDim.x + threadIdx.x;
    if (e < N_EDGES) atomicAdd(&g_cnt[ei[N_EDGES + e]], 1);
}

// ---------------- launch 1: single-block scan -> rowptr, cursor, dis ----------------
__global__ void k_scanall() {           // <<<1, 1024>>>
    __shared__ int s[1024];
    const int CH = (N_NODES + 1023) / 1024;   // 49
    int t = threadIdx.x;
    int base = t * CH;
    int sum = 0;
    for (int j = 0; j < CH; j++) {
        int i = base + j;
        if (i < N_NODES) sum += g_cnt[i] + 1;       // +1 self loop
    }
    s[t] = sum;
    __syncthreads();
    for (int off = 1; off < 1024; off <<= 1) {
        int v = 0;
        if (t >= off) v = s[t - off];
        __syncthreads();
        s[t] += v;
        __syncthreads();
    }
    int run = s[t] - sum;               // exclusive prefix for this thread's chunk
    for (int j = 0; j < CH; j++) {
        int i = base + j;
        if (i < N_NODES) {
            int deg = g_cnt[i] + 1;
            g_rowptr[i] = run;
            g_cursor[i] = run;
            g_dis[i] = rsqrtf((float)deg);
            run += deg;
        }
    }
    if (t == 1023) g_rowptr[N_NODES] = s[1023];
}

// ---------------- launch 2: fill CSR with precomputed weights; re-zero g_cnt ----------------
__global__ void k_fill(const int* __restrict__ ei) {
    int idx = blockIdx.x * blockDim.x + threadIdx.x;
    if (idx < N_NODES) g_cnt[idx] = 0;            // restore invariant for next replay
    if (idx >= TOT_E) return;
    int src, tgt; float w;
    if (idx < N_EDGES) {
        src = ei[idx]; tgt = ei[N_EDGES + idx];
        w = g_dis[src] * g_dis[tgt];
    } else {
        src = tgt = idx - N_EDGES;
        float d = g_dis[src];
        w = d * d;
    }
    int pos = atomicAdd(&g_cursor[tgt], 1);
    g_edges[pos] = make_int2(src, __float_as_int(w));
}

// ---------------- launches 3-5: fused GCN layer: gather (CSR) -> GEMM -> bias+relu ----------------
// block = 32 rows x 128 cols, 256 threads; thread tile 8 rows x 2 cols (low regs -> high occupancy)
__global__ void __launch_bounds__(256) k_layer(
        const float* __restrict__ in, const float* __restrict__ W,
        const float* __restrict__ bias, float* __restrict__ out) {
    __shared__ float As[32 * 128];
    int tid = threadIdx.x, lane = tid & 31, wp = tid >> 5;
    int r0 = blockIdx.x * 32;
    const float4* in4 = (const float4*)in;
    // gather phase: warp per row (8 warps, 4 passes), lane covers 4 features
    for (int rr = wp; rr < 32; rr += 8) {
        int i = r0 + rr;
        float4 acc = make_float4(0.f, 0.f, 0.f, 0.f);
        if (i < N_NODES) {
            int s = g_rowptr[i], e = g_rowptr[i + 1];
            #pragma unroll 4
            for (int idx = s; idx < e; idx++) {
                int2 ed = g_edges[idx];
                float wt = __int_as_float(ed.y);
                float4 v = in4[ed.x * 32 + lane];
                acc.x += wt * v.x; acc.y += wt * v.y;
                acc.z += wt * v.z; acc.w += wt * v.w;
            }
        }
        ((float4*)(As + rr * 128))[lane] = acc;
    }
    __syncthreads();
    // GEMM phase: thread = 8 rows x 2 cols
    int j0 = tid & 63;
    int rg = tid >> 6;                      // 0..3 -> rows rg*8 .. rg*8+7
    const float* Asb = &As[rg * 8 * 128];
    float acc0[8], acc1[8];
    #pragma unroll
    for (int r = 0; r < 8; r++) { acc0[r] = 0.f; acc1[r] = 0.f; }
    #pragma unroll 4
    for (int k = 0; k < 128; k++) {
        float w0 = W[k * 128 + j0];
        float w1 = W[k * 128 + j0 + 64];
        #pragma unroll
        for (int r = 0; r < 8; r++) {
            float a = Asb[r * 128 + k];
            acc0[r] += a * w0;
            acc1[r] += a * w1;
        }
    }
    float b0 = bias[j0], b1 = bias[j0 + 64];
    #pragma unroll
    for (int r = 0; r < 8; r++) {
        int rr = r0 + rg * 8 + r;
        if (rr < N_NODES) {
            out[rr * 128 + j0]      = fmaxf(acc0[r] + b0, 0.f);
            out[rr * 128 + j0 + 64] = fmaxf(acc1[r] + b1, 0.f);
        }
    }
}

// ---------------- launch 6: set2set prep (states + graph ranges + LSTM weight transpose) ----------------
__global__ void k_prep2(const int* __restrict__ batch,
                        const float* __restrict__ Wih, const float* __restrict__ Whh,
                        const float* __restrict__ bih, const float* __restrict__ bhh) {
    int idx = blockIdx.x * blockDim.x + threadIdx.x;
    if (idx < 384 * 512) {
        int k = idx / 512, j = idx % 512;
        g_WT[idx] = (k < 256) ? Wih[j * 256 + k] : Whh[j * 128 + (k - 256)];
    }
    if (idx < 512) g_gbias[idx] = bih[idx] + bhh[idx];
    if (idx < NGR * HID) { g_hs[idx] = 0.f; g_cs[idx] = 0.f; }
    if (idx < NGR * QSD) g_qstar[idx] = 0.f;
    if (idx <= NGR) {
        if (idx == NGR) g_gptr[idx] = N_NODES;
        else {
            int lo = 0, hi = N_NODES;
            while (lo < hi) {
                int mid = (lo + hi) >> 1;
                if (batch[mid] < idx) lo = mid + 1; else hi = mid;
            }
            g_gptr[idx] = lo;
        }
    }
}

__device__ __forceinline__ float sigmoidf_(float x) { return 1.f / (1.f + __expf(-x)); }

// ---------------- fused LSTM-gates GEMM + gate nonlinearity (8 graphs / block, 64 blocks) ----------------
__global__ void __launch_bounds__(512) k_gates_lstm() {
    __shared__ float sA[8 * 384];     // 12 KB  [q_star | hs] inputs
    __shared__ float sg[8 * 512];     // 16 KB  gate pre-activations
    int tid = threadIdx.x;
    int gb = blockIdx.x;              // 0..63
    for (int idx = tid; idx < 8 * 384; idx += 512) {
        int g = idx / 384, k = idx % 384;
        int gg = gb * 8 + g;
        sA[idx] = (k < 256) ? g_qstar[gg * 256 + k] : g_hs[gg * 128 + (k - 256)];
    }
    __syncthreads();
    int j = tid;                      // 0..511 gate index
    float acc[8];
    #pragma unroll
    for (int g = 0; g < 8; g++) acc[g] = 0.f;
    #pragma unroll 4
    for (int k = 0; k < 384; k++) {
        float wv = g_WT[k * 512 + j];
        #pragma unroll
        for (int g = 0; g < 8; g++) acc[g] += sA[g * 384 + k] * wv;
    }
    float bb = g_gbias[j];
    #pragma unroll
    for (int g = 0; g < 8; g++) sg[g * 512 + j] = acc[g] + bb;
    __syncthreads();
    // LSTM cell update: 8 graphs x 128 dims = 1024 items over 512 threads
    #pragma unroll
    for (int t = 0; t < 2; t++) {
        int idx = tid + t * 512;
        int g = idx >> 7, jj = idx & 127;
        int gg = gb * 8 + g;
        const float* gr = &sg[g * 512];
        float ig = gr[jj], fg = gr[jj + 128], ga = gr[jj + 256], og = gr[jj + 384];
        int gidx = gg * 128 + jj;
        float c = sigmoidf_(fg) * g_cs[gidx] + sigmoidf_(ig) * tanhf(ga);
        g_cs[gidx] = c;
        float q = sigmoidf_(og) * tanhf(c);
        g_hs[gidx] = q;
        g_qstar[gg * 256 + jj] = q;   // q part of q_star
    }
}

// ---------------- attention + segment softmax + weighted sum (block per graph, 256 threads) ----------------
__global__ void __launch_bounds__(256) k_attn(const float* __restrict__ h) {
    __shared__ float sq[128];
    __shared__ float swmax[8];
    __shared__ float semax;
    __shared__ float sr[256];
    __shared__ float sa[2];
    int g = blockIdx.x;
    int tid = threadIdx.x;
    int lane = tid & 31, warp = tid >> 5;
    if (tid < 128) sq[tid] = g_hs[g * 128 + tid];
    __syncthreads();
    int s = g_gptr[g], e = g_gptr[g + 1];
    if (s >= e) {                        // empty graph -> r = 0
        if (tid < 128) g_qstar[g * 256 + 128 + tid] = 0.f;
        return;
    }
    // pass 1: e_i = <h_i, q>, warp per node (8 warps)
    float lmax = -INFINITY;
    float4 qv = ((const float4*)sq)[lane];
    const float4* h4 = (const float4*)h;
    for (int i = s + warp; i < e; i += 8) {
        float4 hv = h4[i * 32 + lane];
        float d = hv.x * qv.x + hv.y * qv.y + hv.z * qv.z + hv.w * qv.w;
        #pragma unroll
        for (int o = 16; o > 0; o >>= 1) d += __shfl_xor_sync(0xffffffffu, d, o);
        if (lane == 0) g_escr[i] = d;
        lmax = fmaxf(lmax, d);
    }
    if (lane == 0) swmax[warp] = lmax;
    __syncthreads();
    if (tid == 0) {
        float m = swmax[0];
        #pragma unroll
        for (int w = 1; w < 8; w++) m = fmaxf(m, swmax[w]);
        semax = m;
    }
    __syncthreads();
    float emax = semax;
    // pass 2: two thread-groups split the node range; dim per thread
    int grp = tid >> 7, dim = tid & 127;
    int half = (e - s) >> 1;
    int b0 = (grp == 0) ? s : s + half;
    int b1 = (grp == 0) ? s + half : e;
    float r = 0.f, asum = 0.f;
    #pragma unroll 4
    for (int i = b0; i < b1; i++) {
        float w = __expf(g_escr[i] - emax);
        asum += w;
        r += w * h[i * 128 + dim];
    }
    sr[tid] = r;
    if (dim == 0) sa[grp] = asum;
    __syncthreads();
    if (tid < 128) {
        float rt = sr[tid] + sr[128 + tid];
        float at = sa[0] + sa[1];
        g_qstar[g * 256 + 128 + tid] = rt / (at > 0.f ? at : 1.f);
    }
}

// ---------------- fused MLP head + log_softmax (block per graph) ----------------
__global__ void __launch_bounds__(128) k_mlp(
        const float* __restrict__ L1w, const float* __restrict__ L1b,
        const float* __restrict__ L2w, const float* __restrict__ L2b,
        const float* __restrict__ L3w, const float* __restrict__ L3b,
        float* __restrict__ out) {
    __shared__ float a[256];
    __shared__ float y1[128];
    __shared__ float y2[64];
    __shared__ float ys[NCLS];
    int g = blockIdx.x, j = threadIdx.x;
    a[j] = g_qstar[g * 256 + j];
    a[j + 128] = g_qstar[g * 256 + 128 + j];
    __syncthreads();
    float acc = L1b[j];
    #pragma unroll 4
    for (int k = 0; k < 256; k++) acc += a[k] * L1w[k * 128 + j];
    y1[j] = fmaxf(acc, 0.f);
    __syncthreads();
    if (j < 64) {
        float acc2 = L2b[j];
        #pragma unroll 4
        for (int k = 0; k < 128; k++) acc2 += y1[k] * L2w[k * 64 + j];
        y2[j] = fmaxf(acc2, 0.f);
    }
    __syncthreads();
    if (j < NCLS) {
        float acc3 = L3b[j];
        #pragma unroll
        for (int k = 0; k < 64; k++) acc3 += y2[k] * L3w[k * NCLS + j];
        ys[j] = acc3;
    }
    __syncthreads();
    if (j < NCLS) {
        float m = ys[0];
        #pragma unroll
        for (int k = 1; k < NCLS; k++) m = fmaxf(m, ys[k]);
        float se = 0.f;
        #pragma unroll
        for (int k = 0; k < NCLS; k++) se += expf(ys[k] - m);
        out[g * NCLS + j] = ys[j] - m - logf(se);
    }
}

// ---------------- launcher ----------------
extern "C" void kernel_launch(void* const* d_in, const int* in_sizes, int n_in,
                              void* d_out, int out_size) {
    const float* x     = (const float*)d_in[0];
    const int*   ei    = (const int*)  d_in[1];
    const int*   batch = (const int*)  d_in[2];
    const float* W1 = (const float*)d_in[3];  const float* b1 = (const float*)d_in[4];
    const float* W2 = (const float*)d_in[5];  const float* b2 = (const float*)d_in[6];
    const float* W3 = (const float*)d_in[7];  const float* b3 = (const float*)d_in[8];
    const float* Wih = (const float*)d_in[9]; const float* Whh = (const float*)d_in[10];
    const float* bih = (const float*)d_in[11];const float* bhh = (const float*)d_in[12];
    const float* L1w = (const float*)d_in[13];const float* L1b = (const float*)d_in[14];
    const float* L2w = (const float*)d_in[15];const float* L2b = (const float*)d_in[16];
    const float* L3w = (const float*)d_in[17];const float* L3b = (const float*)d_in[18];
    float* out = (float*)d_out;

    int layer_grid = (N_NODES + 31) / 32;

    // CSR build
    k_hist<<<(N_EDGES + 255) / 256, 256>>>(ei);        // 0
    k_scanall<<<1, 1024>>>();                          // 1
    k_fill<<<(TOT_E + 255) / 256, 256>>>(ei);          // 2

    // fused GCN layers (index 5 = ncu capture target)
    k_layer<<<layer_grid, 256>>>(x,    W1, b1, g_hA);  // 3
    k_layer<<<layer_grid, 256>>>(g_hA, W2, b2, g_hB);  // 4
    k_layer<<<layer_grid, 256>>>(g_hB, W3, b3, g_hA);  // 5

    // set2set prep (states, graph ranges, LSTM weights)
    k_prep2<<<(384 * 512 + 255) / 256, 256>>>(batch, Wih, Whh, bih, bhh); // 6

    // Set2Set (4 processing steps); final node embedding = g_hA
    for (int step = 0; step < 4; step++) {
        k_gates_lstm<<<64, 512>>>();
        k_attn<<<NGR, 256>>>(g_hA);
    }

    // fused MLP head + log_softmax
    k_mlp<<<NGR, 128>>>(L1w, L1b, L2w, L2b, L3w, L3b, out);
}

// round 6
// speedup vs baseline: 2.1777x; 1.0146x over previous
#include <cuda_runtime.h>
#include <math.h>

#define N_NODES 50000
#define N_EDGES 800000
#define TOT_E   (N_EDGES + N_NODES)
#define HID     128
#define NGR     512
#define QSD     256       // 2*HID
#define NCLS    10

// ---------------- scratch (device globals; no runtime allocation) ----------------
__device__ int   g_cnt[N_NODES];          // edge-count histogram (zero at load; re-zeroed inside k_fill)
__device__ int   g_rowptr[N_NODES + 1];
__device__ int   g_cursor[N_NODES];
__device__ float g_dis[N_NODES];          // rsqrt(deg incl self-loop)
__device__ int2  g_edges[TOT_E];          // CSR by target: {src, weight-as-int}
__device__ int   g_gptr[NGR + 1];         // per-graph node ranges (batch sorted)
__device__ float g_hA[N_NODES * HID];
__device__ float g_hB[N_NODES * HID];
__device__ float g_escr[N_NODES];
__device__ float g_WT[384 * 512];         // transposed [Wih|Whh]
__device__ float g_gbias[512];            // bih+bhh
__device__ float g_hs[NGR * HID];
__device__ float g_cs[NGR * HID];
__device__ float g_qstar[NGR * QSD];

// ---------------- launch 0: degree histogram ----------------
__global__ void k_hist(const int* __restrict__ ei) {
    int e = blockIdx.x * blockDim.x + threadIdx.x;
    if (e < N_EDGES) atomicAdd(&g_cnt[ei[N_EDGES + e]], 1);
}

// ---------------- launch 1: single-block scan -> rowptr, cursor, dis ----------------
__global__ void k_scanall() {           // <<<1, 1024>>>
    __shared__ int s[1024];
    const int CH = (N_NODES + 1023) / 1024;   // 49
    int t = threadIdx.x;
    int base = t * CH;
    int sum = 0;
    for (int j = 0; j < CH; j++) {
        int i = base + j;
        if (i < N_NODES) sum += g_cnt[i] + 1;       // +1 self loop
    }
    s[t] = sum;
    __syncthreads();
    for (int off = 1; off < 1024; off <<= 1) {
        int v = 0;
        if (t >= off) v = s[t - off];
        __syncthreads();
        s[t] += v;
        __syncthreads();
    }
    int run = s[t] - sum;               // exclusive prefix for this thread's chunk
    for (int j = 0; j < CH; j++) {
        int i = base + j;
        if (i < N_NODES) {
            int deg = g_cnt[i] + 1;
            g_rowptr[i] = run;
            g_cursor[i] = run;
            g_dis[i] = rsqrtf((float)deg);
            run += deg;
        }
    }
    if (t == 1023) g_rowptr[N_NODES] = s[1023];
}

// ---------------- launch 2: fill CSR with precomputed weights; re-zero g_cnt ----------------
__global__ void k_fill(const int* __restrict__ ei) {
    int idx = blockIdx.x * blockDim.x + threadIdx.x;
    if (idx < N_NODES) g_cnt[idx] = 0;            // restore invariant for next replay
    if (idx >= TOT_E) return;
    int src, tgt; float w;
    if (idx < N_EDGES) {
        src = ei[idx]; tgt = ei[N_EDGES + idx];
        w = g_dis[src] * g_dis[tgt];
    } else {
        src = tgt = idx - N_EDGES;
        float d = g_dis[src];
        w = d * d;
    }
    int pos = atomicAdd(&g_cursor[tgt], 1);
    g_edges[pos] = make_int2(src, __float_as_int(w));
}

// ---------------- launches 3-5: fused GCN layer: gather (CSR) -> GEMM -> bias+relu ----------------
// block = 32 rows x 128 cols, 256 threads
// gather: warp/row, 8-wide edge batching (independent loads -> MLP ~8)
// GEMM: thread tile 4 rows x 4 cols, float4 weight loads (FMA:LDS = 16:5)
__global__ void __launch_bounds__(256) k_layer(
        const float* __restrict__ in, const float* __restrict__ W,
        const float* __restrict__ bias, float* __restrict__ out) {
    __shared__ float As[32 * 128];
    int tid = threadIdx.x, lane = tid & 31, wp = tid >> 5;
    int r0 = blockIdx.x * 32;
    const float4* in4 = (const float4*)in;
    // ---- gather phase ----
    for (int rr = wp; rr < 32; rr += 8) {
        int i = r0 + rr;
        float4 acc = make_float4(0.f, 0.f, 0.f, 0.f);
        if (i < N_NODES) {
            int s = g_rowptr[i], e = g_rowptr[i + 1];
            int idx = s;
            for (; idx + 8 <= e; idx += 8) {
                int2 e0 = g_edges[idx+0], e1 = g_edges[idx+1];
                int2 e2 = g_edges[idx+2], e3 = g_edges[idx+3];
                int2 e4 = g_edges[idx+4], e5 = g_edges[idx+5];
                int2 e6 = g_edges[idx+6], e7 = g_edges[idx+7];
                float4 v0 = in4[e0.x * 32 + lane];
                float4 v1 = in4[e1.x * 32 + lane];
                float4 v2 = in4[e2.x * 32 + lane];
                float4 v3 = in4[e3.x * 32 + lane];
                float4 v4 = in4[e4.x * 32 + lane];
                float4 v5 = in4[e5.x * 32 + lane];
                float4 v6 = in4[e6.x * 32 + lane];
                float4 v7 = in4[e7.x * 32 + lane];
                float w0 = __int_as_float(e0.y), w1 = __int_as_float(e1.y);
                float w2 = __int_as_float(e2.y), w3 = __int_as_float(e3.y);
                float w4 = __int_as_float(e4.y), w5 = __int_as_float(e5.y);
                float w6 = __int_as_float(e6.y), w7 = __int_as_float(e7.y);
                acc.x += w0*v0.x + w1*v1.x + w2*v2.x + w3*v3.x
                       + w4*v4.x + w5*v5.x + w6*v6.x + w7*v7.x;
                acc.y += w0*v0.y + w1*v1.y + w2*v2.y + w3*v3.y
                       + w4*v4.y + w5*v5.y + w6*v6.y + w7*v7.y;
                acc.z += w0*v0.z + w1*v1.z + w2*v2.z + w3*v3.z
                       + w4*v4.z + w5*v5.z + w6*v6.z + w7*v7.z;
                acc.w += w0*v0.w + w1*v1.w + w2*v2.w + w3*v3.w
                       + w4*v4.w + w5*v5.w + w6*v6.w + w7*v7.w;
            }
            for (; idx < e; idx++) {
                int2 ed = g_edges[idx];
                float wt = __int_as_float(ed.y);
                float4 v = in4[ed.x * 32 + lane];
                acc.x += wt * v.x; acc.y += wt * v.y;
                acc.z += wt * v.z; acc.w += wt * v.w;
            }
        }
        ((float4*)(As + rr * 128))[lane] = acc;
    }
    __syncthreads();
    // ---- GEMM phase: 4 rows x 4 cols per thread ----
    int jg = tid & 31;                    // col group: cols 4*jg .. 4*jg+3
    int rg = tid >> 5;                    // row group: rows 4*rg .. 4*rg+3
    const float4* W4 = (const float4*)W;
    float a0[4], a1[4], a2[4], a3[4];     // acc[row][col]
    #pragma unroll
    for (int c = 0; c < 4; c++) { a0[c]=0.f; a1[c]=0.f; a2[c]=0.f; a3[c]=0.f; }
    const float* Asb = &As[rg * 4 * 128];
    #pragma unroll 4
    for (int k = 0; k < 128; k++) {
        float4 w = W4[k * 32 + jg];
        float x0 = Asb[k], x1 = Asb[128 + k], x2 = Asb[256 + k], x3 = Asb[384 + k];
        a0[0] += x0*w.x; a0[1] += x0*w.y; a0[2] += x0*w.z; a0[3] += x0*w.w;
        a1[0] += x1*w.x; a1[1] += x1*w.y; a1[2] += x1*w.z; a1[3] += x1*w.w;
        a2[0] += x2*w.x; a2[1] += x2*w.y; a2[2] += x2*w.z; a2[3] += x2*w.w;
        a3[0] += x3*w.x; a3[1] += x3*w.y; a3[2] += x3*w.z; a3[3] += x3*w.w;
    }
    float4 b = ((const float4*)bias)[jg];
    float4* out4 = (float4*)out;
    int row = r0 + rg * 4;
    if (row + 0 < N_NODES) out4[(row+0)*32 + jg] = make_float4(
        fmaxf(a0[0]+b.x,0.f), fmaxf(a0[1]+b.y,0.f), fmaxf(a0[2]+b.z,0.f), fmaxf(a0[3]+b.w,0.f));
    if (row + 1 < N_NODES) out4[(row+1)*32 + jg] = make_float4(
        fmaxf(a1[0]+b.x,0.f), fmaxf(a1[1]+b.y,0.f), fmaxf(a1[2]+b.z,0.f), fmaxf(a1[3]+b.w,0.f));
    if (row + 2 < N_NODES) out4[(row+2)*32 + jg] = make_float4(
        fmaxf(a2[0]+b.x,0.f), fmaxf(a2[1]+b.y,0.f), fmaxf(a2[2]+b.z,0.f), fmaxf(a2[3]+b.w,0.f));
    if (row + 3 < N_NODES) out4[(row+3)*32 + jg] = make_float4(
        fmaxf(a3[0]+b.x,0.f), fmaxf(a3[1]+b.y,0.f), fmaxf(a3[2]+b.z,0.f), fmaxf(a3[3]+b.w,0.f));
}

// ---------------- launch 6: set2set prep (states + graph ranges + LSTM weight transpose) ----------------
__global__ void k_prep2(const int* __restrict__ batch,
                        const float* __restrict__ Wih, const float* __restrict__ Whh,
                        const float* __restrict__ bih, const float* __restrict__ bhh) {
    int idx = blockIdx.x * blockDim.x + threadIdx.x;
    if (idx < 384 * 512) {
        int k = idx / 512, j = idx % 512;
        g_WT[idx] = (k < 256) ? Wih[j * 256 + k] : Whh[j * 128 + (k - 256)];
    }
    if (idx < 512) g_gbias[idx] = bih[idx] + bhh[idx];
    if (idx < NGR * HID) { g_hs[idx] = 0.f; g_cs[idx] = 0.f; }
    if (idx < NGR * QSD) g_qstar[idx] = 0.f;
    if (idx <= NGR) {
        if (idx == NGR) g_gptr[idx] = N_NODES;
        else {
            int lo = 0, hi = N_NODES;
            while (lo < hi) {
                int mid = (lo + hi) >> 1;
                if (batch[mid] < idx) lo = mid + 1; else hi = mid;
            }
            g_gptr[idx] = lo;
        }
    }
}

__device__ __forceinline__ float sigmoidf_(float x) { return 1.f / (1.f + __expf(-x)); }

// ---------------- fused LSTM-gates GEMM + nonlinearity (4 graphs / block, 128 blocks) ----------------
__global__ void __launch_bounds__(512) k_gates_lstm() {
    __shared__ float sA[4 * 384];     // [q_star | hs] inputs
    __shared__ float sg[4 * 512];     // gate pre-activations
    int tid = threadIdx.x;
    int gb = blockIdx.x;              // 0..127
    for (int idx = tid; idx < 4 * 384; idx += 512) {
        int g = idx / 384, k = idx % 384;
        int gg = gb * 4 + g;
        sA[idx] = (k < 256) ? g_qstar[gg * 256 + k] : g_hs[gg * 128 + (k - 256)];
    }
    __syncthreads();
    int j = tid;                      // 0..511 gate index
    float acc0 = 0.f, acc1 = 0.f, acc2 = 0.f, acc3 = 0.f;
    #pragma unroll 4
    for (int k = 0; k < 384; k++) {
        float wv = g_WT[k * 512 + j];
        acc0 += sA[k]        * wv;
        acc1 += sA[384 + k]  * wv;
        acc2 += sA[768 + k]  * wv;
        acc3 += sA[1152 + k] * wv;
    }
    float bb = g_gbias[j];
    sg[j]        = acc0 + bb;
    sg[512 + j]  = acc1 + bb;
    sg[1024 + j] = acc2 + bb;
    sg[1536 + j] = acc3 + bb;
    __syncthreads();
    // LSTM cell update: 4 graphs x 128 dims = 512 items, one per thread
    int g = tid >> 7, jj = tid & 127;
    int gg = gb * 4 + g;
    const float* gr = &sg[g * 512];
    float ig = gr[jj], fg = gr[jj + 128], ga = gr[jj + 256], og = gr[jj + 384];
    int gidx = gg * 128 + jj;
    float c = sigmoidf_(fg) * g_cs[gidx] + sigmoidf_(ig) * tanhf(ga);
    g_cs[gidx] = c;
    float q = sigmoidf_(og) * tanhf(c);
    g_hs[gidx] = q;
    g_qstar[gg * 256 + jj] = q;       // q part of q_star
}

// ---------------- attention (+ fused MLP head on the last step), block per graph ----------------
__global__ void __launch_bounds__(256) k_attn(
        const float* __restrict__ h, int do_mlp,
        const float* __restrict__ L1w, const float* __restrict__ L1b,
        const float* __restrict__ L2w, const float* __restrict__ L2b,
        const float* __restrict__ L3w, const float* __restrict__ L3b,
        float* __restrict__ out) {
    __shared__ float sq[128];
    __shared__ float swmax[8];
    __shared__ float semax;
    __shared__ float sr[256];
    __shared__ float sa[2];
    __shared__ float rfin[128];
    __shared__ float y1[128];
    __shared__ float y2[64];
    __shared__ float ys[NCLS];
    int g = blockIdx.x;
    int tid = threadIdx.x;
    int lane = tid & 31, warp = tid >> 5;
    if (tid < 128) sq[tid] = g_hs[g * 128 + tid];
    __syncthreads();
    int s = g_gptr[g], e = g_gptr[g + 1];
    if (s < e) {
        // pass 1: e_i = <h_i, q>, warp per node (8 warps)
        float lmax = -INFINITY;
        float4 qv = ((const float4*)sq)[lane];
        const float4* h4 = (const float4*)h;
        for (int i = s + warp; i < e; i += 8) {
            float4 hv = h4[i * 32 + lane];
            float d = hv.x * qv.x + hv.y * qv.y + hv.z * qv.z + hv.w * qv.w;
            #pragma unroll
            for (int o = 16; o > 0; o >>= 1) d += __shfl_xor_sync(0xffffffffu, d, o);
            if (lane == 0) g_escr[i] = d;
            lmax = fmaxf(lmax, d);
        }
        if (lane == 0) swmax[warp] = lmax;
        __syncthreads();
        if (tid == 0) {
            float m = swmax[0];
            #pragma unroll
            for (int w = 1; w < 8; w++) m = fmaxf(m, swmax[w]);
            semax = m;
        }
        __syncthreads();
        float emax = semax;
        // pass 2: two thread-groups split the node range; dim per thread
        int grp = tid >> 7, dim = tid & 127;
        int half = (e - s) >> 1;
        int b0 = (grp == 0) ? s : s + half;
        int b1 = (grp == 0) ? s + half : e;
        float r = 0.f, asum = 0.f;
        #pragma unroll 4
        for (int i = b0; i < b1; i++) {
            float w = __expf(g_escr[i] - emax);
            asum += w;
            r += w * h[i * 128 + dim];
        }
        sr[tid] = r;
        if (dim == 0) sa[grp] = asum;
        __syncthreads();
        if (tid < 128) {
            float rt = sr[tid] + sr[128 + tid];
            float at = sa[0] + sa[1];
            rfin[tid] = rt / (at > 0.f ? at : 1.f);
        }
    } else {
        if (tid < 128) rfin[tid] = 0.f;   // empty graph -> r = 0
    }
    __syncthreads();
    if (!do_mlp) {
        if (tid < 128) g_qstar[g * 256 + 128 + tid] = rfin[tid];
        return;
    }
    // ---- fused MLP head + log_softmax on the final step ----
    if (tid < 128) {
        float acc = L1b[tid];
        #pragma unroll 4
        for (int k = 0; k < 128; k++) acc += sq[k] * L1w[k * 128 + tid];
        #pragma unroll 4
        for (int k = 0; k < 128; k++) acc += rfin[k] * L1w[(128 + k) * 128 + tid];
        y1[tid] = fmaxf(acc, 0.f);
    }
    __syncthreads();
    if (tid < 64) {
        float acc = L2b[tid];
        #pragma unroll 4
        for (int k = 0; k < 128; k++) acc += y1[k] * L2w[k * 64 + tid];
        y2[tid] = fmaxf(acc, 0.f);
    }
    __syncthreads();
    if (tid < NCLS) {
        float acc = L3b[tid];
        #pragma unroll
        for (int k = 0; k < 64; k++) acc += y2[k] * L3w[k * NCLS + tid];
        ys[tid] = acc;
    }
    __syncthreads();
    if (tid < NCLS) {
        float m = ys[0];
        #pragma unroll
        for (int k = 1; k < NCLS; k++) m = fmaxf(m, ys[k]);
        float se = 0.f;
        #pragma unroll
        for (int k = 0; k < NCLS; k++) se += expf(ys[k] - m);
        out[g * NCLS + tid] = ys[tid] - m - logf(se);
    }
}

// ---------------- launcher ----------------
extern "C" void kernel_launch(void* const* d_in, const int* in_sizes, int n_in,
                              void* d_out, int out_size) {
    const float* x     = (const float*)d_in[0];
    const int*   ei    = (const int*)  d_in[1];
    const int*   batch = (const int*)  d_in[2];
    const float* W1 = (const float*)d_in[3];  const float* b1 = (const float*)d_in[4];
    const float* W2 = (const float*)d_in[5];  const float* b2 = (const float*)d_in[6];
    const float* W3 = (const float*)d_in[7];  const float* b3 = (const float*)d_in[8];
    const float* Wih = (const float*)d_in[9]; const float* Whh = (const float*)d_in[10];
    const float* bih = (const float*)d_in[11];const float* bhh = (const float*)d_in[12];
    const float* L1w = (const float*)d_in[13];const float* L1b = (const float*)d_in[14];
    const float* L2w = (const float*)d_in[15];const float* L2b = (const float*)d_in[16];
    const float* L3w = (const float*)d_in[17];const float* L3b = (const float*)d_in[18];
    float* out = (float*)d_out;

    int layer_grid = (N_NODES + 31) / 32;

    // CSR build
    k_hist<<<(N_EDGES + 255) / 256, 256>>>(ei);        // 0
    k_scanall<<<1, 1024>>>();                          // 1
    k_fill<<<(TOT_E + 255) / 256, 256>>>(ei);          // 2

    // fused GCN layers (index 5 = ncu capture target)
    k_layer<<<layer_grid, 256>>>(x,    W1, b1, g_hA);  // 3
    k_layer<<<layer_grid, 256>>>(g_hA, W2, b2, g_hB);  // 4
    k_layer<<<layer_grid, 256>>>(g_hB, W3, b3, g_hA);  // 5

    // set2set prep (states, graph ranges, LSTM weights)
    k_prep2<<<(384 * 512 + 255) / 256, 256>>>(batch, Wih, Whh, bih, bhh); // 6

    // Set2Set (4 processing steps); final step fuses the MLP head + log_softmax
    for (int step = 0; step < 4; step++) {
        k_gates_lstm<<<128, 512>>>();
        k_attn<<<NGR, 256>>>(g_hA, step == 3 ? 1 : 0,
                             L1w, L1b, L2w, L2b, L3w, L3b, out);
    }
}